// round 15
// baseline (speedup 1.0000x reference)
#include <cuda_runtime.h>
#include <cuda_bf16.h>
#include <math_constants.h>

#define D       32000
#define NROWS   4096
#define TA      256
#define NWARP   8
#define CHUNK4  1000            // float4s per warp chunk
#define SUBF4   125             // float4s per sub-step
#define NSUB    8
#define CAP_L   24              // per-lane slot capacity (exp 8.35; >=24 -> flagged fallback)
#define WFL     (CAP_L * 32)    // floats per warp region (768)
#define PAD     (17 * 32)       // overrun pad
#define CCAP    3072            // per-row pruned-candidate capacity (typ ~600)
#define RC      24              // solve: register-staged candidates per lane
#define FBW     1500            // fallback smem candidates per warp (12000/row total)
#define NBIS    5
#define NNEWT   4
#define XT      1.5f            // coarse threshold (X scale); valid iff rowmaxX > XT+2 (checked)
#define CHI     0.005590169943749474f   // (1/32000)^0.5

__device__ float g_cand[(size_t)NROWS * CCAP];   // 50 MB scratch (~10 MB touched)
__device__ int   g_cnt[NROWS];                   // -1 => fallback row (solve kernel, block-wide)
__device__ float g_rmx[NROWS];                   // rmaxX (X scale)
__device__ float g_loss[NROWS];
__device__ int   g_done;                         // zero-init; last CTA resets

__device__ __forceinline__ float warp_sum(float v) {
    #pragma unroll
    for (int o = 16; o; o >>= 1) v += __shfl_xor_sync(0xffffffffu, v, o);
    return v;
}
__device__ __forceinline__ float warp_max(float v) {
    #pragma unroll
    for (int o = 16; o; o >>= 1) v = fmaxf(v, __shfl_xor_sync(0xffffffffu, v, o));
    return v;
}

#define FOR16(OP) OP(c0.x) OP(c0.y) OP(c0.z) OP(c0.w) \
                  OP(c1.x) OP(c1.y) OP(c1.z) OP(c1.w) \
                  OP(c2.x) OP(c2.y) OP(c2.z) OP(c2.w) \
                  OP(c3.x) OP(c3.y) OP(c3.z) OP(c3.w)

// ============================================================================
// Kernel F: streaming filter -> pruned candidates to scratch (R12, unchanged)
// ============================================================================
__global__ void __launch_bounds__(TA, 6) filter_kernel(const float* __restrict__ X)
{
    __shared__ float s_col[NWARP * WFL + PAD];   // ~26.7 KB per-lane stride-32 slots
    __shared__ float s_max[NWARP];
    __shared__ int   s_wcnt[NWARP];
    __shared__ int   s_fb;

    const int row  = blockIdx.x;
    const int tid  = threadIdx.x;
    const int lane = tid & 31;
    const int wid  = tid >> 5;

    if (tid == 0) s_fb = 0;
    __syncthreads();

    const float4* __restrict__ Xr4 = reinterpret_cast<const float4*>(X + (size_t)row * D);
    const float4* __restrict__ W4  = Xr4 + wid * CHUNK4;

    float* const wreg = s_col + wid * WFL;
    float* const base = wreg + lane;
    float* const plim = base + CAP_L * 32;

    const float4 FILL = make_float4(-CUDART_INF_F, -CUDART_INF_F, -CUDART_INF_F, -CUDART_INF_F);
    #define LOADSUB(dst0,dst1,dst2,dst3,sub) do {                        \
        int _b = (sub) * SUBF4;                                          \
        dst0 = W4[_b + lane];                                            \
        dst1 = W4[_b + lane + 32];                                       \
        dst2 = W4[_b + lane + 64];                                       \
        dst3 = (lane + 96 < SUBF4) ? W4[_b + lane + 96] : FILL;          \
    } while (0)

    float4 a0, a1, a2, a3, b0, b1, b2, b3;
    LOADSUB(a0, a1, a2, a3, 0);
    LOADSUB(b0, b1, b2, b3, 1);

    float* p = base;
    #pragma unroll
    for (int sub = 0; sub < NSUB; sub++) {
        float4 c0 = a0, c1 = a1, c2 = a2, c3 = a3;
        a0 = b0; a1 = b1; a2 = b2; a3 = b3;
        if (sub + 2 < NSUB) LOADSUB(b0, b1, b2, b3, sub + 2);

        #define WR(a) { bool q = (a) > XT; if (q) { *p = (a); p += 32; } }
        FOR16(WR)
        #undef WR
        if (p > plim) p = plim;     // clamp once per sub
    }
    #undef LOADSUB

    const int kl = (int)((p - base) >> 5);
    if (kl >= CAP_L) s_fb = 1;                    // benign race; conservative

    const int J0 = __reduce_max_sync(0xffffffffu, kl);
    {
        float mx = -CUDART_INF_F;
        for (int j = 0; j < J0; j++) {
            float v = base[j * 32];
            mx = fmaxf(mx, (j < kl) ? v : -CUDART_INF_F);
        }
        mx = warp_max(mx);
        if (lane == 0) s_max[wid] = mx;           // X scale
    }
    __syncthreads();

    float rmaxX = s_max[0];
    #pragma unroll
    for (int w = 1; w < NWARP; w++) rmaxX = fmaxf(rmaxX, s_max[w]);
    const bool fbA = (s_fb != 0) || !(rmaxX - 2.0f > XT + 1e-4f);

    if (fbA) {
        if (tid == 0) g_cnt[row] = -1;
        return;
    }

    // prune (X > rmaxX-2) + in-place warp compaction -> contiguous Xa in wreg
    int cw = 0;
    {
        const float tX = rmaxX - 2.0f - 1e-5f;    // margin only adds zero-contributing elems
        for (int j = 0; j < J0; j++) {
            float v = base[j * 32];
            bool pred = (j < kl) && (v > tX);
            unsigned m = __ballot_sync(0xffffffffu, pred);
            if (pred) wreg[cw + __popc(m & ((1u << lane) - 1u))] = 0.5f * v;
            cw += __popc(m);
        }
        if (lane == 0) s_wcnt[wid] = cw;
    }
    __syncthreads();

    int off = 0, tot = 0;
    #pragma unroll
    for (int w = 0; w < NWARP; w++) {
        int c = s_wcnt[w];
        tot += c;
        if (w < wid) off += c;
    }
    if (tot > CCAP) {
        if (tid == 0) g_cnt[row] = -1;
        return;
    }

    float* dst = g_cand + (size_t)row * CCAP + off;
    for (int i = lane; i < cw; i += 32) dst[i] = wreg[i];

    if (tid == 0) { g_cnt[row] = tot; g_rmx[row] = rmaxX; }
}

// ============================================================================
// Kernel S: warp-per-row solve; fallback rows: 2-pass smem compact + solve.
// ============================================================================
extern __shared__ float s_fbuf[];   // NWARP * FBW floats (48 KB): fallback candidates (Xa)

__global__ void __launch_bounds__(TA) solve_kernel(const float* __restrict__ X,
                                                   const int*   __restrict__ target,
                                                   float*       __restrict__ out)
{
    __shared__ float s_F[2][NWARP], s_G[2][NWARP];
    __shared__ float s_p3[3][NWARP];
    __shared__ float s_red[NWARP];
    __shared__ int   s_cnt8[NWARP];
    __shared__ int   s_wc[NWARP];
    __shared__ int   s_last;

    const int tid  = threadIdx.x;
    const int lane = tid & 31;
    const int wid  = tid >> 5;
    const int row  = blockIdx.x * NWARP + wid;

    const int cnt = g_cnt[row];
    if (lane == 0) s_cnt8[wid] = cnt;

    if (cnt >= 0) {
        // ---- normal path: one warp per row, register-staged candidates ----
        const float* __restrict__ Xr = X + (size_t)row * D;
        float xt = 0.f;
        if (lane == 0) xt = Xr[target[row]];

        const float rmax = 0.5f * g_rmx[row];
        const float* cand = g_cand + (size_t)row * CCAP;

        float C[RC];
        const bool ext = (cnt > RC * 32);
        #pragma unroll
        for (int r = 0; r < RC; r++) {
            int i = lane + 32 * r;
            C[r] = (i < cnt) ? cand[i] : -1e30f;  // pad -> contributes exactly 0
        }

        const float tau_lo0 = rmax - 1.0f;
        const float tau_hi  = rmax - CHI;
        float tau_lo = tau_lo0;
        float dm = tau_hi - tau_lo;
        float tau_m = tau_lo;

        #pragma unroll 1
        for (int it = 0; it < NBIS + NNEWT; it++) {
            const bool newton = (it >= NBIS);
            float te;
            if (!newton) { dm *= 0.5f; te = tau_lo + dm; }
            else         { te = tau_m; }

            float F = 0.f, G = 0.f;
            #pragma unroll
            for (int r = 0; r < RC; r++) {
                float t = fmaxf(C[r] - te, 0.f);
                F = fmaf(t, t, F); G += t;
            }
            if (ext) {
                for (int i = RC * 32 + lane; i < cnt; i += 32) {
                    float t = fmaxf(cand[i] - te, 0.f);
                    F = fmaf(t, t, F); G += t;
                }
            }
            #pragma unroll
            for (int o = 16; o; o >>= 1) {
                F += __shfl_xor_sync(0xffffffffu, F, o);
                G += __shfl_xor_sync(0xffffffffu, G, o);
            }
            const float f = F - 1.0f;
            if (!newton) {
                if (f >= 0.f) tau_lo = te;         // f(tau_lo) >= 0 invariant
                if (it == NBIS - 1) tau_m = tau_lo;
            } else {
                float tn = te + f / (2.0f * G);    // f' = -2G; convex: stays left of root
                tau_m = fminf(fmaxf(tn, tau_lo0), tau_hi);
            }
        }

        float S = 0.f, A15 = 0.f, PX = 0.f;
        #pragma unroll
        for (int r = 0; r < RC; r++) {
            float v = C[r];
            float t = fmaxf(v - tau_m, 0.f);
            float pr = t * t;
            S += pr; A15 = fmaf(pr, t, A15); PX = fmaf(pr, v, PX);
        }
        if (ext) {
            for (int i = RC * 32 + lane; i < cnt; i += 32) {
                float v = cand[i];
                float t = fmaxf(v - tau_m, 0.f);
                float pr = t * t;
                S += pr; A15 = fmaf(pr, t, A15); PX = fmaf(pr, v, PX);
            }
        }
        #pragma unroll
        for (int o = 16; o; o >>= 1) {
            S   += __shfl_xor_sync(0xffffffffu, S,   o);
            A15 += __shfl_xor_sync(0xffffffffu, A15, o);
            PX  += __shfl_xor_sync(0xffffffffu, PX,  o);
        }
        if (lane == 0) {
            float sum_p15 = A15 / (S * sqrtf(S));
            float omega   = (1.0f - sum_p15) / 0.75f;   // alpha*(alpha-1) = 0.75
            g_loss[row] = omega + 2.0f * PX / S - xt;
        }
    }
    __syncthreads();

    // ---- fallback rows (rare): 2 row passes + smem-candidate solve ----
    for (int rr = 0; rr < NWARP; rr++) {
        if (s_cnt8[rr] >= 0) continue;
        const int frow = blockIdx.x * NWARP + rr;
        const float* __restrict__ Xr = X + (size_t)frow * D;

        // pass 1: exact row max, block-wide
        float m = -CUDART_INF_F;
        for (int i = tid; i < D; i += TA) m = fmaxf(m, Xr[i]);
        m = warp_max(m);
        if (lane == 0) s_red[wid] = m;
        __syncthreads();
        float rmaxX = s_red[0];
        #pragma unroll
        for (int w = 1; w < NWARP; w++) rmaxX = fmaxf(rmaxX, s_red[w]);
        const float rmax = 0.5f * rmaxX;
        __syncthreads();

        // pass 2: compact true candidates (X > rmaxX-2) into per-warp smem segments
        float* seg = s_fbuf + wid * FBW;
        int cw = 0;
        {
            const float tX = rmaxX - 2.0f - 1e-5f;
            for (int i = wid * 32 + lane; i < D; i += TA) {
                float v = Xr[i];
                bool pred = v > tX;
                unsigned mm = __ballot_sync(0xffffffffu, pred);
                if (pred) {
                    int pos = cw + __popc(mm & ((1u << lane) - 1u));
                    if (pos < FBW) seg[pos] = 0.5f * v;
                }
                cw += __popc(mm);
            }
            if (lane == 0) s_wc[wid] = cw;
        }
        __syncthreads();

        bool ovf = false;
        #pragma unroll
        for (int w = 0; w < NWARP; w++) ovf |= (s_wc[w] > FBW);   // P ~ e^-199; guard anyway
        const int mycw = ovf ? 0 : s_wc[wid];

        const float tau_lo0 = rmax - 1.0f;
        const float tau_hi  = rmax - CHI;
        float tau_lo = tau_lo0;
        float dm = tau_hi - tau_lo;
        float tau_m = tau_lo;
        int pb = 0;

        #pragma unroll 1
        for (int it = 0; it < NBIS + NNEWT; it++) {
            const bool newton = (it >= NBIS);
            float te;
            if (!newton) { dm *= 0.5f; te = tau_lo + dm; }
            else         { te = tau_m; }

            float F = 0.f, G = 0.f;
            if (!ovf) {
                for (int j = lane; j < mycw; j += 32) {
                    float t = fmaxf(seg[j] - te, 0.f);
                    F = fmaf(t, t, F); G += t;
                }
            } else {
                for (int i = tid; i < D; i += TA) {
                    float t = fmaxf(0.5f * Xr[i] - te, 0.f);
                    F = fmaf(t, t, F); G += t;
                }
            }
            #pragma unroll
            for (int o = 16; o; o >>= 1) {
                F += __shfl_xor_sync(0xffffffffu, F, o);
                G += __shfl_xor_sync(0xffffffffu, G, o);
            }
            if (lane == 0) { s_F[pb][wid] = F; s_G[pb][wid] = G; }
            __syncthreads();
            float Ft = 0.f, Gt = 0.f;
            #pragma unroll
            for (int w = 0; w < NWARP; w++) { Ft += s_F[pb][w]; Gt += s_G[pb][w]; }
            const float f = Ft - 1.0f;

            if (!newton) {
                if (f >= 0.f) tau_lo = te;
                if (it == NBIS - 1) tau_m = tau_lo;
            } else {
                float tn = te + f / (2.0f * Gt);
                tau_m = fminf(fmaxf(tn, tau_lo0), tau_hi);
            }
            pb ^= 1;
        }

        float S = 0.f, A15 = 0.f, PX = 0.f;
        if (!ovf) {
            for (int j = lane; j < mycw; j += 32) {
                float v = seg[j];
                float t = fmaxf(v - tau_m, 0.f);
                float pr = t * t;
                S += pr; A15 = fmaf(pr, t, A15); PX = fmaf(pr, v, PX);
            }
        } else {
            for (int i = tid; i < D; i += TA) {
                float v = 0.5f * Xr[i];
                float t = fmaxf(v - tau_m, 0.f);
                float pr = t * t;
                S += pr; A15 = fmaf(pr, t, A15); PX = fmaf(pr, v, PX);
            }
        }
        S = warp_sum(S); A15 = warp_sum(A15); PX = warp_sum(PX);
        if (lane == 0) { s_p3[0][wid] = S; s_p3[1][wid] = A15; s_p3[2][wid] = PX; }
        __syncthreads();
        if (tid == 0) {
            float St = 0.f, At = 0.f, Pt = 0.f;
            #pragma unroll
            for (int w = 0; w < NWARP; w++) { St += s_p3[0][w]; At += s_p3[1][w]; Pt += s_p3[2][w]; }
            float sum_p15 = At / (St * sqrtf(St));
            float omega   = (1.0f - sum_p15) / 0.75f;
            g_loss[frow] = omega + 2.0f * Pt / St - Xr[target[frow]];
        }
        __syncthreads();
    }

    // ---- last CTA computes the mean ----
    if (tid == 0) {
        __threadfence();
        int t = atomicAdd(&g_done, 1);
        s_last = (t == (NROWS / NWARP) - 1);
    }
    __syncthreads();
    if (s_last) {
        if (tid == 0) g_done = 0;
        __threadfence();
        float a = 0.f;
        #pragma unroll 4
        for (int i = tid; i < NROWS; i += TA) a += g_loss[i];
        a = warp_sum(a);
        if (lane == 0) s_red[wid] = a;
        __syncthreads();
        if (tid == 0) {
            float tot = 0.f;
            #pragma unroll
            for (int w = 0; w < NWARP; w++) tot += s_red[w];
            out[0] = tot / (float)NROWS;
        }
    }
}

// ============================================================================
extern "C" void kernel_launch(void* const* d_in, const int* in_sizes, int n_in,
                              void* d_out, int out_size)
{
    const float* X      = (const float*)d_in[0];
    const int*   target = (const int*)  d_in[1];
    float*       out    = (float*)d_out;

    const int dynsmem = NWARP * FBW * (int)sizeof(float);   // 48000 B
    cudaFuncSetAttribute(solve_kernel, cudaFuncAttributeMaxDynamicSharedMemorySize, dynsmem);

    filter_kernel<<<NROWS, TA>>>(X);
    solve_kernel<<<NROWS / NWARP, TA, dynsmem>>>(X, target, out);
}

// round 16
// speedup vs baseline: 1.0331x; 1.0331x over previous
#include <cuda_runtime.h>
#include <cuda_bf16.h>
#include <math_constants.h>

#define D       32000
#define D4      8000
#define NROWS   4096
#define TA      256
#define NWARP   8
#define CHUNK4  1000            // float4s per warp chunk (filter)
#define SUBF4   125             // float4s per sub-step (filter)
#define NSUB    8
#define CAP_L   24              // filter per-lane slot capacity
#define WFL     (CAP_L * 32)
#define PAD     (17 * 32)
#define CCAP    3072            // per-row pruned-candidate capacity (typ ~450)
#define RC      24              // solve: register-staged candidates per lane
#define FBC     48              // fallback per-lane column capacity (48*32*8*4B = 48KB)
#define NBIS    5
#define NNEWT   4
#define XT      1.5f            // coarse threshold (X scale); valid iff rowmaxX > XT+2 (checked)
#define CHI     0.005590169943749474f   // (1/32000)^0.5

__device__ float g_cand[(size_t)NROWS * CCAP];
__device__ int   g_cnt[NROWS];                   // -1 => fallback row
__device__ float g_rmx[NROWS];
__device__ float g_loss[NROWS];
__device__ int   g_done;

__device__ __forceinline__ float warp_sum(float v) {
    #pragma unroll
    for (int o = 16; o; o >>= 1) v += __shfl_xor_sync(0xffffffffu, v, o);
    return v;
}
__device__ __forceinline__ float warp_max(float v) {
    #pragma unroll
    for (int o = 16; o; o >>= 1) v = fmaxf(v, __shfl_xor_sync(0xffffffffu, v, o));
    return v;
}

#define FOR16(OP) OP(c0.x) OP(c0.y) OP(c0.z) OP(c0.w) \
                  OP(c1.x) OP(c1.y) OP(c1.z) OP(c1.w) \
                  OP(c2.x) OP(c2.y) OP(c2.z) OP(c2.w) \
                  OP(c3.x) OP(c3.y) OP(c3.z) OP(c3.w)

// ============================================================================
// Kernel F: streaming filter -> pruned candidates to scratch (unchanged)
// ============================================================================
__global__ void __launch_bounds__(TA, 6) filter_kernel(const float* __restrict__ X)
{
    __shared__ float s_col[NWARP * WFL + PAD];
    __shared__ float s_max[NWARP];
    __shared__ int   s_wcnt[NWARP];
    __shared__ int   s_fb;

    const int row  = blockIdx.x;
    const int tid  = threadIdx.x;
    const int lane = tid & 31;
    const int wid  = tid >> 5;

    if (tid == 0) s_fb = 0;
    __syncthreads();

    const float4* __restrict__ Xr4 = reinterpret_cast<const float4*>(X + (size_t)row * D);
    const float4* __restrict__ W4  = Xr4 + wid * CHUNK4;

    float* const wreg = s_col + wid * WFL;
    float* const base = wreg + lane;
    float* const plim = base + CAP_L * 32;

    const float4 FILL = make_float4(-CUDART_INF_F, -CUDART_INF_F, -CUDART_INF_F, -CUDART_INF_F);
    #define LOADSUB(dst0,dst1,dst2,dst3,sub) do {                        \
        int _b = (sub) * SUBF4;                                          \
        dst0 = W4[_b + lane];                                            \
        dst1 = W4[_b + lane + 32];                                       \
        dst2 = W4[_b + lane + 64];                                       \
        dst3 = (lane + 96 < SUBF4) ? W4[_b + lane + 96] : FILL;          \
    } while (0)

    float4 a0, a1, a2, a3, b0, b1, b2, b3;
    LOADSUB(a0, a1, a2, a3, 0);
    LOADSUB(b0, b1, b2, b3, 1);

    float* p = base;
    #pragma unroll
    for (int sub = 0; sub < NSUB; sub++) {
        float4 c0 = a0, c1 = a1, c2 = a2, c3 = a3;
        a0 = b0; a1 = b1; a2 = b2; a3 = b3;
        if (sub + 2 < NSUB) LOADSUB(b0, b1, b2, b3, sub + 2);

        #define WR(a) { bool q = (a) > XT; if (q) { *p = (a); p += 32; } }
        FOR16(WR)
        #undef WR
        if (p > plim) p = plim;
    }
    #undef LOADSUB

    const int kl = (int)((p - base) >> 5);
    if (kl >= CAP_L) s_fb = 1;

    const int J0 = __reduce_max_sync(0xffffffffu, kl);
    {
        float mx = -CUDART_INF_F;
        for (int j = 0; j < J0; j++) {
            float v = base[j * 32];
            mx = fmaxf(mx, (j < kl) ? v : -CUDART_INF_F);
        }
        mx = warp_max(mx);
        if (lane == 0) s_max[wid] = mx;
    }
    __syncthreads();

    float rmaxX = s_max[0];
    #pragma unroll
    for (int w = 1; w < NWARP; w++) rmaxX = fmaxf(rmaxX, s_max[w]);
    const bool fbA = (s_fb != 0) || !(rmaxX - 2.0f > XT + 1e-4f);

    if (fbA) {
        if (tid == 0) g_cnt[row] = -1;
        return;
    }

    int cw = 0;
    {
        const float tX = rmaxX - 2.0f - 1e-5f;
        for (int j = 0; j < J0; j++) {
            float v = base[j * 32];
            bool pred = (j < kl) && (v > tX);
            unsigned m = __ballot_sync(0xffffffffu, pred);
            if (pred) wreg[cw + __popc(m & ((1u << lane) - 1u))] = 0.5f * v;
            cw += __popc(m);
        }
        if (lane == 0) s_wcnt[wid] = cw;
    }
    __syncthreads();

    int off = 0, tot = 0;
    #pragma unroll
    for (int w = 0; w < NWARP; w++) {
        int c = s_wcnt[w];
        tot += c;
        if (w < wid) off += c;
    }
    if (tot > CCAP) {
        if (tid == 0) g_cnt[row] = -1;
        return;
    }

    float* dst = g_cand + (size_t)row * CCAP + off;
    for (int i = lane; i < cw; i += 32) dst[i] = wreg[i];

    if (tid == 0) { g_cnt[row] = tot; g_rmx[row] = rmaxX; }
}

// ============================================================================
// Kernel S: warp-per-row solve (hoisted loads, split accumulators);
// fallback rows: high-MLP 2-pass + lane-column solve.
// ============================================================================
extern __shared__ float s_fbuf[];   // NWARP*FBC*32 floats (48 KB) fallback columns

__global__ void __launch_bounds__(TA) solve_kernel(const float* __restrict__ X,
                                                   const int*   __restrict__ target,
                                                   float*       __restrict__ out)
{
    __shared__ float s_F[2][NWARP], s_G[2][NWARP];
    __shared__ float s_p3[3][NWARP];
    __shared__ float s_red[NWARP];
    __shared__ int   s_cnt8[NWARP];
    __shared__ int   s_ovf;
    __shared__ int   s_last;

    const int tid  = threadIdx.x;
    const int lane = tid & 31;
    const int wid  = tid >> 5;
    const int row  = blockIdx.x * NWARP + wid;

    const float* __restrict__ Xr = X + (size_t)row * D;

    // ---- hoisted, branch-free loads: all independent of cnt ----
    const int   cnt  = g_cnt[row];
    const float rmxX = g_rmx[row];
    float xt = 0.f;
    if (lane == 0) xt = Xr[target[row]];
    const float* cand = g_cand + (size_t)row * CCAP;
    float C[RC];
    #pragma unroll
    for (int r = 0; r < RC; r++) C[r] = cand[lane + 32 * r];    // always in-bounds scratch
    #pragma unroll
    for (int r = 0; r < RC; r++) if (lane + 32 * r >= cnt) C[r] = -1e30f;  // mask late

    if (lane == 0) s_cnt8[wid] = cnt;

    if (cnt >= 0) {
        const float rmax = 0.5f * rmxX;
        const bool  ext  = (cnt > RC * 32);

        const float tau_lo0 = rmax - 1.0f;
        const float tau_hi  = rmax - CHI;
        float tau_lo = tau_lo0;
        float dm = tau_hi - tau_lo;
        float tau_m = tau_lo;

        #pragma unroll 1
        for (int it = 0; it < NBIS + NNEWT; it++) {
            const bool newton = (it >= NBIS);
            float te;
            if (!newton) { dm *= 0.5f; te = tau_lo + dm; }
            else         { te = tau_m; }

            float F0 = 0.f, F1 = 0.f, F2 = 0.f, F3 = 0.f, G0 = 0.f, G1 = 0.f;
            #pragma unroll
            for (int r = 0; r < RC; r += 4) {
                float t0 = fmaxf(C[r]     - te, 0.f);
                float t1 = fmaxf(C[r + 1] - te, 0.f);
                float t2 = fmaxf(C[r + 2] - te, 0.f);
                float t3 = fmaxf(C[r + 3] - te, 0.f);
                F0 = fmaf(t0, t0, F0); F1 = fmaf(t1, t1, F1);
                F2 = fmaf(t2, t2, F2); F3 = fmaf(t3, t3, F3);
                G0 += t0 + t2;         G1 += t1 + t3;
            }
            float F = (F0 + F1) + (F2 + F3);
            float G = G0 + G1;
            if (ext) {
                for (int i = RC * 32 + lane; i < cnt; i += 32) {
                    float t = fmaxf(cand[i] - te, 0.f);
                    F = fmaf(t, t, F); G += t;
                }
            }
            #pragma unroll
            for (int o = 16; o; o >>= 1) {
                F += __shfl_xor_sync(0xffffffffu, F, o);
                G += __shfl_xor_sync(0xffffffffu, G, o);
            }
            const float f = F - 1.0f;
            if (!newton) {
                if (f >= 0.f) tau_lo = te;
                if (it == NBIS - 1) tau_m = tau_lo;
            } else {
                float tn = te + f / (2.0f * G);
                tau_m = fminf(fmaxf(tn, tau_lo0), tau_hi);
            }
        }

        float S = 0.f, A15 = 0.f, PX = 0.f;
        #pragma unroll
        for (int r = 0; r < RC; r++) {
            float v = C[r];
            float t = fmaxf(v - tau_m, 0.f);
            float pr = t * t;
            S += pr; A15 = fmaf(pr, t, A15); PX = fmaf(pr, v, PX);
        }
        if (ext) {
            for (int i = RC * 32 + lane; i < cnt; i += 32) {
                float v = cand[i];
                float t = fmaxf(v - tau_m, 0.f);
                float pr = t * t;
                S += pr; A15 = fmaf(pr, t, A15); PX = fmaf(pr, v, PX);
            }
        }
        #pragma unroll
        for (int o = 16; o; o >>= 1) {
            S   += __shfl_xor_sync(0xffffffffu, S,   o);
            A15 += __shfl_xor_sync(0xffffffffu, A15, o);
            PX  += __shfl_xor_sync(0xffffffffu, PX,  o);
        }
        if (lane == 0) {
            float sum_p15 = A15 / (S * sqrtf(S));
            float omega   = (1.0f - sum_p15) / 0.75f;
            g_loss[row] = omega + 2.0f * PX / S - xt;
        }
    }
    __syncthreads();

    // ---- fallback rows (rare): high-MLP 2-pass + lane-column solve ----
    for (int rr = 0; rr < NWARP; rr++) {
        if (s_cnt8[rr] >= 0) continue;
        const int frow = blockIdx.x * NWARP + rr;
        const float*  __restrict__ Fr  = X + (size_t)frow * D;
        const float4* __restrict__ Fr4 = reinterpret_cast<const float4*>(Fr);
        if (tid == 0) s_ovf = 0;

        // pass 1: exact row max, float4 + unroll-4 (MLP 16/thread)
        float4 m4 = make_float4(-CUDART_INF_F, -CUDART_INF_F, -CUDART_INF_F, -CUDART_INF_F);
        #pragma unroll 4
        for (int i = tid; i < D4; i += TA) {
            float4 v = Fr4[i];
            m4.x = fmaxf(m4.x, v.x); m4.y = fmaxf(m4.y, v.y);
            m4.z = fmaxf(m4.z, v.z); m4.w = fmaxf(m4.w, v.w);
        }
        float m = fmaxf(fmaxf(m4.x, m4.y), fmaxf(m4.z, m4.w));
        m = warp_max(m);
        if (lane == 0) s_red[wid] = m;
        __syncthreads();
        float rmaxX = s_red[0];
        #pragma unroll
        for (int w = 1; w < NWARP; w++) rmaxX = fmaxf(rmaxX, s_red[w]);
        const float rmax = 0.5f * rmaxX;
        __syncthreads();

        // pass 2: per-lane stride-32 column compaction (3 inst/elem, no ballot chain)
        float* const col = s_fbuf + (wid * FBC) * 32 + lane;
        int c = 0;
        {
            const float tX = rmaxX - 2.0f - 1e-5f;
            #pragma unroll 2
            for (int i = tid; i < D4; i += TA) {
                float4 v = Fr4[i];
                #define WRC(a) { if ((a) > tX) { if (c < FBC) col[c * 32] = 0.5f * (a); c++; } }
                WRC(v.x) WRC(v.y) WRC(v.z) WRC(v.w)
                #undef WRC
            }
        }
        if (c > FBC) s_ovf = 1;                       // astronomically rare
        const int J = __reduce_max_sync(0xffffffffu, (c < FBC) ? c : FBC);
        for (int j = c; j < J; j++) col[j * 32] = -1e30f;   // pad -> contributes 0
        __syncthreads();
        const bool ovf = (s_ovf != 0);

        const float tau_lo0 = rmax - 1.0f;
        const float tau_hi  = rmax - CHI;
        float tau_lo = tau_lo0;
        float dm = tau_hi - tau_lo;
        float tau_m = tau_lo;
        int pb = 0;

        #pragma unroll 1
        for (int it = 0; it < NBIS + NNEWT; it++) {
            const bool newton = (it >= NBIS);
            float te;
            if (!newton) { dm *= 0.5f; te = tau_lo + dm; }
            else         { te = tau_m; }

            float F = 0.f, G = 0.f;
            if (!ovf) {
                for (int j = 0; j < J; j++) {
                    float t = fmaxf(col[j * 32] - te, 0.f);
                    F = fmaf(t, t, F); G += t;
                }
            } else {
                #pragma unroll 4
                for (int i = tid; i < D; i += TA) {
                    float t = fmaxf(0.5f * Fr[i] - te, 0.f);
                    F = fmaf(t, t, F); G += t;
                }
            }
            #pragma unroll
            for (int o = 16; o; o >>= 1) {
                F += __shfl_xor_sync(0xffffffffu, F, o);
                G += __shfl_xor_sync(0xffffffffu, G, o);
            }
            if (lane == 0) { s_F[pb][wid] = F; s_G[pb][wid] = G; }
            __syncthreads();
            float Ft = 0.f, Gt = 0.f;
            #pragma unroll
            for (int w = 0; w < NWARP; w++) { Ft += s_F[pb][w]; Gt += s_G[pb][w]; }
            const float f = Ft - 1.0f;

            if (!newton) {
                if (f >= 0.f) tau_lo = te;
                if (it == NBIS - 1) tau_m = tau_lo;
            } else {
                float tn = te + f / (2.0f * Gt);
                tau_m = fminf(fmaxf(tn, tau_lo0), tau_hi);
            }
            pb ^= 1;
        }

        float S = 0.f, A15 = 0.f, PX = 0.f;
        if (!ovf) {
            for (int j = 0; j < J; j++) {
                float v = col[j * 32];
                float t = fmaxf(v - tau_m, 0.f);
                float pr = t * t;
                S += pr; A15 = fmaf(pr, t, A15); PX = fmaf(pr, v, PX);
            }
        } else {
            #pragma unroll 4
            for (int i = tid; i < D; i += TA) {
                float v = 0.5f * Fr[i];
                float t = fmaxf(v - tau_m, 0.f);
                float pr = t * t;
                S += pr; A15 = fmaf(pr, t, A15); PX = fmaf(pr, v, PX);
            }
        }
        S = warp_sum(S); A15 = warp_sum(A15); PX = warp_sum(PX);
        if (lane == 0) { s_p3[0][wid] = S; s_p3[1][wid] = A15; s_p3[2][wid] = PX; }
        __syncthreads();
        if (tid == 0) {
            float St = 0.f, At = 0.f, Pt = 0.f;
            #pragma unroll
            for (int w = 0; w < NWARP; w++) { St += s_p3[0][w]; At += s_p3[1][w]; Pt += s_p3[2][w]; }
            float sum_p15 = At / (St * sqrtf(St));
            float omega   = (1.0f - sum_p15) / 0.75f;
            g_loss[frow] = omega + 2.0f * Pt / St - Fr[target[frow]];
        }
        __syncthreads();
    }

    // ---- last CTA computes the mean ----
    if (tid == 0) {
        __threadfence();
        int t = atomicAdd(&g_done, 1);
        s_last = (t == (NROWS / NWARP) - 1);
    }
    __syncthreads();
    if (s_last) {
        if (tid == 0) g_done = 0;
        __threadfence();
        float a = 0.f;
        #pragma unroll 4
        for (int i = tid; i < NROWS; i += TA) a += g_loss[i];
        a = warp_sum(a);
        if (lane == 0) s_red[wid] = a;
        __syncthreads();
        if (tid == 0) {
            float tot = 0.f;
            #pragma unroll
            for (int w = 0; w < NWARP; w++) tot += s_red[w];
            out[0] = tot / (float)NROWS;
        }
    }
}

// ============================================================================
extern "C" void kernel_launch(void* const* d_in, const int* in_sizes, int n_in,
                              void* d_out, int out_size)
{
    const float* X      = (const float*)d_in[0];
    const int*   target = (const int*)  d_in[1];
    float*       out    = (float*)d_out;

    const int dynsmem = NWARP * FBC * 32 * (int)sizeof(float);   // 49152 B
    cudaFuncSetAttribute(solve_kernel, cudaFuncAttributeMaxDynamicSharedMemorySize, dynsmem);

    filter_kernel<<<NROWS, TA>>>(X);
    solve_kernel<<<NROWS / NWARP, TA, dynsmem>>>(X, target, out);
}